// round 6
// baseline (speedup 1.0000x reference)
#include <cuda_runtime.h>

typedef unsigned long long ull;

// Problem constants
constexpr int Tn = 1000, Dd = 64, Nn = 128, Bb = 1000;
constexpr int NCTA = 148, TPB = 256;
constexpr int NWORK = 7 + (NCTA - 1) * 8;       // 1183 worker warps
constexpr int NTASK = 2 * Tn + Bb;              // 2000 bcast + 1000 trace tasks
constexpr size_t REGION4 = (size_t)Bb * Tn * Nn / 4;  // float4 per output region

// KEY INSIGHT: reference broadcasts x_t across all B rows from identical zero
// state => all B rows are identical. Simulate one row; broadcast, OVERLAPPED
// via a persistent producer/consumer kernel.

__device__ float g_inp_cur[Tn * Nn];
__device__ float g_spk[Tn * Nn];
__device__ float g_memh[Tn * Nn];
__device__ float g_trc[Nn];
__device__ int   g_progress;   // steps completed & visible (reset each launch)

// ---------------------------------------------------------------------------
// Kernel A: input currents (1000x64 @ 64x128) + progress reset.
// ---------------------------------------------------------------------------
__global__ void inp_cur_kernel(const float* __restrict__ sig,
                               const float* __restrict__ w_in) {
    int t = blockIdx.x, n = threadIdx.x;
    if (t == 0 && n == 0) g_progress = 0;   // visible before fused kernel (stream order)
    float acc = 0.f;
#pragma unroll
    for (int d = 0; d < Dd; ++d) acc += sig[t * Dd + d] * w_in[d * Nn + n];
    g_inp_cur[t * Nn + n] = acc;
}

__device__ __forceinline__ void fadd2(ull& acc, ull w) {
    asm("add.rn.f32x2 %0, %0, %1;" : "+l"(acc) : "l"(w));
}

__device__ __forceinline__ int ld_prog_acquire() {
    int p;
    asm volatile("ld.acquire.gpu.global.b32 %0, [%1];"
                 : "=r"(p) : "l"(&g_progress) : "memory");
    return p;
}

__device__ __forceinline__ void wait_prog(int target) {
    int p = ld_prog_acquire();
    while (p < target) {
        unsigned ns = 128u * (unsigned)(target - p);
        if (ns > 4096u) ns = 4096u;
        if (ns < 128u)  ns = 128u;
        __nanosleep(ns);
        p = ld_prog_acquire();
    }
}

// ---------------------------------------------------------------------------
// Producer: single-warp sim of one row (lane owns neurons 4l..4l+3).
// sW has 129 rows; row 128 is all zeros (padding target for the unrolled
// sparse spike loop). Publishes progress every 4 steps.
// ---------------------------------------------------------------------------
__device__ void run_sim(const float* __restrict__ sW) {
    const int lane = threadIdx.x;   // 0..31
    float mem[4] = {}, syn[4] = {}, refr[4] = {}, rec[4] = {}, trc[4] = {};

    const float4* __restrict__ xin = reinterpret_cast<const float4*>(g_inp_cur);
    float4* __restrict__ ospk = reinterpret_cast<float4*>(g_spk);
    float4* __restrict__ omem = reinterpret_cast<float4*>(g_memh);
    // row k, lane cols as packed pair: sWu[k*32 + lane]
    const ulonglong2* __restrict__ sWu = reinterpret_cast<const ulonglong2*>(sW);
    const ulonglong2* __restrict__ wp = sWu + lane;

    float4 x = xin[lane];

    for (int t = 0; t < Tn; ++t) {
        const int tn = (t + 1 < Tn) ? (t + 1) : t;
        const float4 xn = __ldg(&xin[tn * 32 + lane]);
        const float xv[4] = {x.x, x.y, x.z, x.w};

        float s[4]; bool kk[4];
#pragma unroll
        for (int j = 0; j < 4; ++j) {
            syn[j] = syn[j] * 0.8f + (xv[j] + rec[j]);
            mem[j] = mem[j] * 0.9f + syn[j] * 0.1f;
            mem[j] = (refr[j] > 0.f) ? 0.f : mem[j];
            refr[j] = fmaxf(refr[j] - 1.f, 0.f);
            kk[j] = mem[j] > 1.0f;
            s[j] = kk[j] ? 1.f : 0.f;
            mem[j] = kk[j] ? 0.f : mem[j];
            refr[j] += s[j] * 2.f;
            trc[j] = trc[j] * 0.95f + s[j];
        }

        unsigned msk[4];
#pragma unroll
        for (int j = 0; j < 4; ++j)
            msk[j] = __ballot_sync(0xFFFFFFFFu, kk[j]);

        ospk[t * 32 + lane] = make_float4(s[0], s[1], s[2], s[3]);
        omem[t * 32 + lane] = make_float4(mem[0], mem[1], mem[2], mem[3]);

        // rec = 0.95*rec + sum_{spiking k} W[k][my 4 cols]
        // neuron k = 4l + j; pads map to zero row k=128.
        ull aAx = 0, aAy = 0, aBx = 0, aBy = 0;
#pragma unroll
        for (int j = 0; j < 4; ++j) {
            unsigned m = msk[j];
            int it = (__popc(m) + 1) >> 1;
            for (; it > 0; --it) {
                const int i1 = __ffs(m); m &= m - 1;
                const int i2 = __ffs(m); m &= m - 1;
                const int k1 = i1 ? 4 * (i1 - 1) + j : 128;
                const int k2 = i2 ? 4 * (i2 - 1) + j : 128;
                const ulonglong2 w1 = wp[k1 * 32];
                const ulonglong2 w2 = wp[k2 * 32];
                fadd2(aAx, w1.x); fadd2(aAy, w1.y);
                fadd2(aBx, w2.x); fadd2(aBy, w2.y);
            }
        }
        fadd2(aAx, aBx); fadd2(aAy, aBy);

        rec[0] = rec[0] * 0.95f + __int_as_float((int)aAx);
        rec[1] = rec[1] * 0.95f + __int_as_float((int)(aAx >> 32));
        rec[2] = rec[2] * 0.95f + __int_as_float((int)aAy);
        rec[3] = rec[3] * 0.95f + __int_as_float((int)(aAy >> 32));

        // Publish completed steps (warp-wide MEMBAR, lane0 store)
        if ((t & 3) == 3 && t != Tn - 1) {
            __threadfence();
            if (lane == 0) *(volatile int*)&g_progress = t + 1;
        }
        x = xn;
    }

    reinterpret_cast<float4*>(g_trc)[lane] =
        make_float4(trc[0], trc[1], trc[2], trc[3]);
    __threadfence();
    if (lane == 0) *(volatile int*)&g_progress = Tn + 1;  // everything visible
}

// ---------------------------------------------------------------------------
// Consumers: broadcast compact rows to all Bb destination rows.
// Task tau < 2000: (t = tau>>1, region = tau&1) -> copy 512B row to 1000 rows.
// Task tau >= 2000: trace row b = tau-2000.
// Tasks processed in ascending tau (= ascending t) per warp.
// ---------------------------------------------------------------------------
__device__ void run_worker(int gid, float* __restrict__ out) {
    const int lane = threadIdx.x & 31;
    float4* __restrict__ out4 = reinterpret_cast<float4*>(out);

    for (int tau = gid; tau < NTASK; tau += NWORK) {
        if (tau < 2 * Tn) {
            const int t = tau >> 1;
            const int region = tau & 1;
            wait_prog(t + 1);
            const float* __restrict__ src = region ? g_memh : g_spk;
            const float4 v = reinterpret_cast<const float4*>(src)[t * 32 + lane];
            float4* dst = out4 + (size_t)region * REGION4 + (size_t)t * 32 + lane;
#pragma unroll 4
            for (int b = 0; b < Bb; ++b) {
                *dst = v;
                dst += Tn * Nn / 4;
            }
        } else {
            wait_prog(Tn + 1);
            const int b = tau - 2 * Tn;
            const float4 v = reinterpret_cast<const float4*>(g_trc)[lane];
            out4[2 * REGION4 + (size_t)b * 32 + lane] = v;
        }
    }
}

// ---------------------------------------------------------------------------
// Fused persistent kernel: grid=148 (1 CTA/SM, all co-resident).
// CTA0: 256 threads load W (+zero row) -> warp0 sims, warps1-7 join workers.
// ---------------------------------------------------------------------------
__global__ __launch_bounds__(TPB, 1)
void fused_kernel(const float* __restrict__ Wrec, float* __restrict__ out) {
    extern __shared__ float sW[];   // 129 * 128 floats (row 128 = zeros)
    const int bid = blockIdx.x, tid = threadIdx.x, wid = tid >> 5;

    if (bid == 0) {
        for (int i = tid; i < (129 * Nn) / 4; i += TPB) {
            float4 v = (i < (Nn * Nn) / 4)
                           ? reinterpret_cast<const float4*>(Wrec)[i]
                           : make_float4(0.f, 0.f, 0.f, 0.f);
            reinterpret_cast<float4*>(sW)[i] = v;
        }
        __syncthreads();
        if (wid == 0) { run_sim(sW); return; }
        run_worker(wid - 1, out);
    } else {
        run_worker(7 + (bid - 1) * 8 + wid, out);
    }
}

// ---------------------------------------------------------------------------
// Harness entry
// ---------------------------------------------------------------------------
extern "C" void kernel_launch(void* const* d_in, const int* in_sizes, int n_in,
                              void* d_out, int out_size) {
    const float* sig   = (const float*)d_in[0];  // (1000, 64)
    const float* w_in  = (const float*)d_in[1];  // (64, 128)
    const float* w_rec = (const float*)d_in[2];  // (128, 128)
    float* out = (float*)d_out;
    (void)in_sizes; (void)n_in; (void)out_size;

    const int smem = 129 * Nn * (int)sizeof(float);  // 66048 B
    cudaFuncSetAttribute(fused_kernel,
                         cudaFuncAttributeMaxDynamicSharedMemorySize, smem);

    inp_cur_kernel<<<Tn, Nn>>>(sig, w_in);
    fused_kernel<<<NCTA, TPB, smem>>>(w_rec, out);
}

// round 7
// speedup vs baseline: 1.4556x; 1.4556x over previous
#include <cuda_runtime.h>

// Problem constants
constexpr int Tn = 1000, Dd = 64, Nn = 128, Bb = 1000;
constexpr size_t REGION4 = (size_t)Bb * Tn * Nn / 4;  // float4 per output region

// KEY INSIGHT: reference broadcasts x_t across all B rows from identical zero
// state => all B rows produce identical outputs. Simulate one row (4 warps,
// latency-parallel), then broadcast at the STG/LTS floor.

__device__ float g_inp_cur[Tn * Nn];  // (T, N) input currents
__device__ float g_spk[Tn * Nn];      // compact spikes (T, N)
__device__ float g_memh[Tn * Nn];     // compact membrane (T, N)
__device__ float g_trc[Nn];           // final trace (N)

// ---------------------------------------------------------------------------
// Kernel A: input currents (1000x64 @ 64x128). ~5us.
// ---------------------------------------------------------------------------
__global__ void inp_cur_kernel(const float* __restrict__ sig,
                               const float* __restrict__ w_in) {
    int t = blockIdx.x, n = threadIdx.x;
    float acc = 0.f;
#pragma unroll
    for (int d = 0; d < Dd; ++d) acc += sig[t * Dd + d] * w_in[d * Nn + n];
    g_inp_cur[t * Nn + n] = acc;
}

// ---------------------------------------------------------------------------
// Kernel B: 4-warp simulation of ONE row. 128 threads, neuron n = tid.
//   - W (128x128) + one zero pad row in SMEM; lane reads only its own column
//     (4B, conflict-free) per spiking source neuron.
//   - Per step: scalar update -> ballot (1 word/warp) -> STS -> syncthreads
//     -> LDS.128 all 4 mask words -> popc-paired sparse accumulate.
//   - Masks double-buffered; one barrier per step.
// ---------------------------------------------------------------------------
__global__ __launch_bounds__(128, 1)
void sim_kernel(const float* __restrict__ Wrec) {
    __shared__ float sW[129 * Nn];            // row 128 = zeros (pad target)
    __shared__ __align__(16) unsigned smask[2][4];

    const int n = threadIdx.x;                // neuron index 0..127
    const int warp = n >> 5;
    const int lane = n & 31;

    // Load W (+ zero pad row)
    {
        float4* dst = reinterpret_cast<float4*>(sW);
        const float4* src = reinterpret_cast<const float4*>(Wrec);
        for (int i = n; i < (129 * Nn) / 4; i += 128)
            dst[i] = (i < (Nn * Nn) / 4) ? src[i] : make_float4(0.f, 0.f, 0.f, 0.f);
    }
    __syncthreads();

    float syn = 0.f, mem = 0.f, refr = 0.f, rec = 0.f, trc = 0.f;

    const float* __restrict__ xin = g_inp_cur;
    float* __restrict__ ospk = g_spk;
    float* __restrict__ omem = g_memh;
    const float* __restrict__ wp = sW + n;    // W[k][n] = wp[k*128]

    float x = xin[n];

    for (int t = 0; t < Tn; ++t) {
        const int tnn = (t + 1 < Tn) ? (t + 1) : t;
        const float xn = __ldg(&xin[tnn * Nn + n]);

        // ---- neuron update (order matches reference) ----
        syn = syn * 0.8f + (x + rec);
        mem = mem * 0.9f + syn * 0.1f;
        mem = (refr > 0.f) ? 0.f : mem;
        refr = fmaxf(refr - 1.f, 0.f);
        const bool k = mem > 1.0f;
        const float s = k ? 1.f : 0.f;
        mem = k ? 0.f : mem;
        refr += s * 2.f;
        trc = trc * 0.95f + s;

        // ---- share spike masks (1 word per warp) ----
        const unsigned mw = __ballot_sync(0xFFFFFFFFu, k);
        const int buf = t & 1;
        if (lane == 0) smask[buf][warp] = mw;
        __syncthreads();
        const uint4 mm = *reinterpret_cast<const uint4*>(&smask[buf][0]);

        // ---- history stores (128B/warp, fire-and-forget) ----
        ospk[t * Nn + n] = s;
        omem[t * Nn + n] = mem;

        // ---- sparse accumulate: rec = 0.95*rec + sum_{spiking src} W[src][n]
        // src = 32*w4 + l; pad -> zero row (offset 16384 - w4*4096 from wp4).
        float accA = 0.f, accB = 0.f;
#pragma unroll
        for (int w4 = 0; w4 < 4; ++w4) {
            unsigned m = (w4 == 0) ? mm.x : (w4 == 1) ? mm.y
                        : (w4 == 2) ? mm.z : mm.w;
            const float* __restrict__ wp4 = wp + w4 * 32 * Nn;
            const int pad = (128 - w4 * 32) * Nn;  // compile-time per w4
            int it = (__popc(m) + 1) >> 1;
            for (; it > 0; --it) {
                const int i1 = __ffs(m); m &= m - 1;
                const int i2 = __ffs(m); m &= m - 1;
                const int o1 = i1 ? (i1 - 1) * Nn : pad;
                const int o2 = i2 ? (i2 - 1) * Nn : pad;
                accA += wp4[o1];
                accB += wp4[o2];
            }
        }
        rec = rec * 0.95f + (accA + accB);

        x = xn;
    }

    g_trc[n] = trc;
}

// ---------------------------------------------------------------------------
// Kernel C: broadcast compact (T,N) spk/mem to all B rows.
//   64000 threads; thread g owns one source float4 (L2-resident) and streams
//   it to 1000 rows. STG.128 issue saturates the chip LTS cap.
// ---------------------------------------------------------------------------
constexpr int BC_THREADS = 448;
constexpr int BC_TASKS = 2 * (Tn * Nn / 4);  // 64000
constexpr int BC_GRID = (BC_TASKS + BC_THREADS - 1) / BC_THREADS;  // 143

__global__ __launch_bounds__(BC_THREADS, 1)
void bcast_kernel(float* __restrict__ out) {
    const int g = blockIdx.x * BC_THREADS + threadIdx.x;
    if (g >= BC_TASKS) return;
    const int region = (g >= Tn * Nn / 4) ? 1 : 0;
    const int src = g - region * (Tn * Nn / 4);
    const float4 v = __ldg(&reinterpret_cast<const float4*>(
                               region ? g_memh : g_spk)[src]);
    float4* __restrict__ dst =
        reinterpret_cast<float4*>(out) + (size_t)region * REGION4 + src;
#pragma unroll 8
    for (int b = 0; b < Bb; ++b)
        dst[(size_t)b * (Tn * Nn / 4)] = v;
}

// ---------------------------------------------------------------------------
// Kernel D: broadcast trace (N) to (B, N). 512KB, ~5us.
// ---------------------------------------------------------------------------
__global__ void trace_kernel(float* __restrict__ out) {
    const int i = blockIdx.x * 256 + threadIdx.x;  // < B*N/4 = 32000
    const float4 v = reinterpret_cast<const float4*>(g_trc)[i & 31];
    reinterpret_cast<float4*>(out + 2 * REGION4 * 4)[i] = v;
}

// ---------------------------------------------------------------------------
// Harness entry
// ---------------------------------------------------------------------------
extern "C" void kernel_launch(void* const* d_in, const int* in_sizes, int n_in,
                              void* d_out, int out_size) {
    const float* sig   = (const float*)d_in[0];  // (1000, 64)
    const float* w_in  = (const float*)d_in[1];  // (64, 128)
    const float* w_rec = (const float*)d_in[2];  // (128, 128)
    float* out = (float*)d_out;
    (void)in_sizes; (void)n_in; (void)out_size;

    inp_cur_kernel<<<Tn, Nn>>>(sig, w_in);
    sim_kernel<<<1, 128>>>(w_rec);
    bcast_kernel<<<BC_GRID, BC_THREADS>>>(out);
    trace_kernel<<<(Bb * Nn / 4) / 256, 256>>>(out);
}

// round 8
// speedup vs baseline: 1.5535x; 1.0673x over previous
#include <cuda_runtime.h>

// Problem constants
constexpr int Tn = 1000, Dd = 64, Nn = 128, Bb = 1000;
constexpr size_t REGION4 = (size_t)Bb * Tn * Nn / 4;  // float4 per output region

// KEY INSIGHT 1: reference broadcasts x_t across all B rows from identical zero
// state => all B rows produce identical outputs. Simulate one row; broadcast.
// KEY INSIGHT 2: the sim was bound by the SERIAL ffs/clear-bit chain (~20 cyc
// per spike, warp-uniform). Replace with parallel lane-compaction: each lane
// writes its own spike index via popc-prefix, one predicated STS.

__device__ float g_inp_cur[Tn * Nn];  // (T, N) input currents
__device__ float g_spk[Tn * Nn];      // compact spikes (T, N)
__device__ float g_memh[Tn * Nn];     // compact membrane (T, N)
__device__ float g_trc[Nn];           // final trace (N)

// ---------------------------------------------------------------------------
// Kernel A: input currents (1000x64 @ 64x128). ~5us.
// ---------------------------------------------------------------------------
__global__ void inp_cur_kernel(const float* __restrict__ sig,
                               const float* __restrict__ w_in) {
    int t = blockIdx.x, n = threadIdx.x;
    float acc = 0.f;
#pragma unroll
    for (int d = 0; d < Dd; ++d) acc += sig[t * Dd + d] * w_in[d * Nn + n];
    g_inp_cur[t * Nn + n] = acc;
}

// ---------------------------------------------------------------------------
// Kernel B: 4-warp simulation of ONE row. 128 threads, neuron n = tid.
//   Per step:
//     scalar update -> ballot -> PARALLEL compaction (lane l writes index
//     byte at popc-prefix slot; 4-byte pad to idx 128 = zero W row; count
//     byte) -> one __syncthreads -> read counts + packed uchar4 index lists
//     -> pipelined sparse accumulate (no serial bit chain, few branches).
//   Lists double-buffered by t&1; one barrier per step.
// ---------------------------------------------------------------------------
__global__ __launch_bounds__(128, 1)
void sim_kernel(const float* __restrict__ Wrec) {
    __shared__ float sW[129 * Nn];                    // row 128 = zeros (pad)
    __shared__ __align__(4) unsigned char sList[2][4][40];  // [buf][warp][slot]
    __shared__ __align__(4) unsigned char sCnt[2][4];       // [buf][warp]

    const int n = threadIdx.x;                // neuron index 0..127
    const int warp = n >> 5;
    const int lane = n & 31;

    // Load W (+ zero pad row)
    {
        float4* dst = reinterpret_cast<float4*>(sW);
        const float4* src = reinterpret_cast<const float4*>(Wrec);
        for (int i = n; i < (129 * Nn) / 4; i += 128)
            dst[i] = (i < (Nn * Nn) / 4) ? src[i] : make_float4(0.f, 0.f, 0.f, 0.f);
    }
    __syncthreads();

    float syn = 0.f, mem = 0.f, refr = 0.f, rec = 0.f, trc = 0.f;

    const float* __restrict__ xin = g_inp_cur;
    float* __restrict__ ospk = g_spk;
    float* __restrict__ omem = g_memh;
    const float* __restrict__ wp = sW + n;    // W[k][n] = wp[k*128]
    const unsigned lt = (lane == 0) ? 0u : (0xFFFFFFFFu >> (32 - lane));

    float x = xin[n];

    for (int t = 0; t < Tn; ++t) {
        const int tnn = (t + 1 < Tn) ? (t + 1) : t;
        const float xn = __ldg(&xin[tnn * Nn + n]);

        // ---- neuron update (order matches reference) ----
        syn = syn * 0.8f + (x + rec);
        mem = mem * 0.9f + syn * 0.1f;
        mem = (refr > 0.f) ? 0.f : mem;
        refr = fmaxf(refr - 1.f, 0.f);
        const bool k = mem > 1.0f;
        const float s = k ? 1.f : 0.f;
        mem = k ? 0.f : mem;
        refr += s * 2.f;
        trc = trc * 0.95f + s;

        // ---- parallel spike-index compaction (own warp's word only) ----
        const unsigned mw = __ballot_sync(0xFFFFFFFFu, k);
        const int buf = t & 1;
        const int c = __popc(mw);
        if (k) sList[buf][warp][__popc(mw & lt)] = (unsigned char)(warp * 32 + lane);
        if (lane < 4) sList[buf][warp][c + lane] = 128;   // pad -> zero row
        if (lane == 0) sCnt[buf][warp] = (unsigned char)c;

        // ---- history stores (128B/warp, fire-and-forget) ----
        ospk[t * Nn + n] = s;
        omem[t * Nn + n] = mem;

        __syncthreads();

        // ---- sparse accumulate: rec = 0.95*rec + sum_{spiking src} W[src][n]
        const unsigned cnts = *reinterpret_cast<const unsigned*>(&sCnt[buf][0]);
        float accA = 0.f, accB = 0.f;
#pragma unroll
        for (int j = 0; j < 4; ++j) {
            const int cj = (cnts >> (8 * j)) & 0xFF;
            const unsigned* __restrict__ lst =
                reinterpret_cast<const unsigned*>(&sList[buf][j][0]);
            for (int i = 0; i < cj; i += 4) {     // padded entries are safe
                const unsigned w4 = lst[i >> 2];
                accA += wp[(w4 & 0xFFu) * Nn];
                accB += wp[((w4 >> 8) & 0xFFu) * Nn];
                accA += wp[((w4 >> 16) & 0xFFu) * Nn];
                accB += wp[(w4 >> 24) * Nn];
            }
        }
        rec = rec * 0.95f + (accA + accB);

        x = xn;
    }

    g_trc[n] = trc;
}

// ---------------------------------------------------------------------------
// Kernel C: broadcast compact (T,N) spk/mem to all B rows.
//   64000 threads; thread g owns one source float4 (L2-resident) and streams
//   it to 1000 rows with streaming stores.
// ---------------------------------------------------------------------------
constexpr int BC_THREADS = 448;
constexpr int BC_TASKS = 2 * (Tn * Nn / 4);  // 64000
constexpr int BC_GRID = (BC_TASKS + BC_THREADS - 1) / BC_THREADS;  // 143

__global__ __launch_bounds__(BC_THREADS, 1)
void bcast_kernel(float* __restrict__ out) {
    const int g = blockIdx.x * BC_THREADS + threadIdx.x;
    if (g >= BC_TASKS) return;
    const int region = (g >= Tn * Nn / 4) ? 1 : 0;
    const int src = g - region * (Tn * Nn / 4);
    const float4 v = __ldg(&reinterpret_cast<const float4*>(
                               region ? g_memh : g_spk)[src]);
    float4* __restrict__ dst =
        reinterpret_cast<float4*>(out) + (size_t)region * REGION4 + src;
#pragma unroll 8
    for (int b = 0; b < Bb; ++b)
        __stcs(&dst[(size_t)b * (Tn * Nn / 4)], v);
}

// ---------------------------------------------------------------------------
// Kernel D: broadcast trace (N) to (B, N). 512KB, ~5us.
// ---------------------------------------------------------------------------
__global__ void trace_kernel(float* __restrict__ out) {
    const int i = blockIdx.x * 256 + threadIdx.x;  // < B*N/4 = 32000
    const float4 v = reinterpret_cast<const float4*>(g_trc)[i & 31];
    __stcs(&reinterpret_cast<float4*>(out + 2 * REGION4 * 4)[i], v);
}

// ---------------------------------------------------------------------------
// Harness entry
// ---------------------------------------------------------------------------
extern "C" void kernel_launch(void* const* d_in, const int* in_sizes, int n_in,
                              void* d_out, int out_size) {
    const float* sig   = (const float*)d_in[0];  // (1000, 64)
    const float* w_in  = (const float*)d_in[1];  // (64, 128)
    const float* w_rec = (const float*)d_in[2];  // (128, 128)
    float* out = (float*)d_out;
    (void)in_sizes; (void)n_in; (void)out_size;

    inp_cur_kernel<<<Tn, Nn>>>(sig, w_in);
    sim_kernel<<<1, 128>>>(w_rec);
    bcast_kernel<<<BC_GRID, BC_THREADS>>>(out);
    trace_kernel<<<(Bb * Nn / 4) / 256, 256>>>(out);
}

// round 9
// speedup vs baseline: 1.6066x; 1.0342x over previous
#include <cuda_runtime.h>

// Problem constants
constexpr int Tn = 1000, Dd = 64, Nn = 128, Bb = 1000;
constexpr int GRID = 296;          // 2 CTAs per SM (148 SMs), all co-resident
constexpr int SLOTS = 4;           // rows per CTA: {c, c+296, c+592, c+888}

// KEY INSIGHT 1: reference broadcasts x_t across all B rows from identical
// zero state => all B rows produce identical outputs.
// KEY INSIGHT 2 (R9): sequential sim-then-broadcast pays both phases; instead
// every CTA runs the (cheap) one-row sim REDUNDANTLY and writes its own rows.
// Zero inter-CTA sync; store traffic hides entirely under the sim's latency.

__device__ float g_inp_cur[Tn * Nn];  // (T, N) input currents

// ---------------------------------------------------------------------------
// Kernel A: input currents (1000x64 @ 64x128). ~5us.
// ---------------------------------------------------------------------------
__global__ void inp_cur_kernel(const float* __restrict__ sig,
                               const float* __restrict__ w_in) {
    int t = blockIdx.x, n = threadIdx.x;
    float acc = 0.f;
#pragma unroll
    for (int d = 0; d < Dd; ++d) acc += sig[t * Dd + d] * w_in[d * Nn + n];
    g_inp_cur[t * Nn + n] = acc;
}

// ---------------------------------------------------------------------------
// Kernel B: monolithic redundant-sim. 128 threads/CTA, neuron n = tid.
//   Per step: scalar update -> ballot -> parallel lane-compaction of spike
//   indices (popc-prefix STS, pad to x4 with idx 128 = zero W row) -> one
//   __syncthreads -> packed uchar4 list walk, pipelined LDS accumulate ->
//   store s/mem for this CTA's 3-4 rows (coalesced 128B STG.32 lines).
//   Lists double-buffered by t&1; one barrier per step.
// ---------------------------------------------------------------------------
__global__ __launch_bounds__(128, 2)
void sim_kernel(const float* __restrict__ Wrec, float* __restrict__ out) {
    extern __shared__ float sW[];                           // 129*128 (row 128 = 0)
    __shared__ __align__(4) unsigned char sList[2][4][40];  // [buf][warp][slot]
    __shared__ __align__(4) unsigned char sCnt[2][4];       // [buf][warp]

    const int n = threadIdx.x;                // neuron index 0..127
    const int warp = n >> 5;
    const int lane = n & 31;
    const int cta = blockIdx.x;

    // Load W (+ zero pad row)
    {
        float4* dst = reinterpret_cast<float4*>(sW);
        const float4* src = reinterpret_cast<const float4*>(Wrec);
        for (int i = n; i < (129 * Nn) / 4; i += 128)
            dst[i] = (i < (Nn * Nn) / 4) ? src[i] : make_float4(0.f, 0.f, 0.f, 0.f);
    }
    __syncthreads();

    // This CTA's rows: cta + 296*i (3 or 4 valid). Precompute spk-base ptrs.
    int nrows = 0;
    float* rsp[SLOTS];
#pragma unroll
    for (int i = 0; i < SLOTS; ++i) {
        const int row = cta + GRID * i;
        if (row < Bb) { rsp[nrows] = out + (size_t)row * Tn * Nn + n; ++nrows; }
    }
    const size_t MEMOFF = (size_t)Bb * Tn * Nn;   // spk -> mem region offset

    float syn = 0.f, mem = 0.f, refr = 0.f, rec = 0.f, trc = 0.f;

    const float* __restrict__ xin = g_inp_cur;
    const float* __restrict__ wp = sW + n;        // W[k][n] = wp[k*128]
    const unsigned lt = (lane == 0) ? 0u : (0xFFFFFFFFu >> (32 - lane));

    float x = xin[n];

    for (int t = 0; t < Tn; ++t) {
        const int tnn = (t + 1 < Tn) ? (t + 1) : t;
        const float xn = __ldg(&xin[tnn * Nn + n]);

        // ---- neuron update (order matches reference) ----
        syn = syn * 0.8f + (x + rec);
        mem = mem * 0.9f + syn * 0.1f;
        mem = (refr > 0.f) ? 0.f : mem;
        refr = fmaxf(refr - 1.f, 0.f);
        const bool k = mem > 1.0f;
        const float s = k ? 1.f : 0.f;
        mem = k ? 0.f : mem;
        refr += s * 2.f;
        trc = trc * 0.95f + s;

        // ---- parallel spike-index compaction (own warp's word only) ----
        const unsigned mw = __ballot_sync(0xFFFFFFFFu, k);
        const int buf = t & 1;
        const int c = __popc(mw);
        if (k) sList[buf][warp][__popc(mw & lt)] = (unsigned char)(warp * 32 + lane);
        if (lane < 4) sList[buf][warp][c + lane] = 128;   // pad -> zero row
        if (lane == 0) sCnt[buf][warp] = (unsigned char)c;

        // ---- store this CTA's rows (fire-and-forget, 128B coalesced) ----
        {
            const int to = t * Nn;
#pragma unroll
            for (int i = 0; i < SLOTS; ++i) {
                if (i < nrows) {
                    rsp[i][to] = s;
                    rsp[i][to + MEMOFF] = mem;
                }
            }
        }

        __syncthreads();

        // ---- sparse accumulate: rec = 0.95*rec + sum_{spiking src} W[src][n]
        const unsigned cnts = *reinterpret_cast<const unsigned*>(&sCnt[buf][0]);
        float accA = 0.f, accB = 0.f;
#pragma unroll
        for (int j = 0; j < 4; ++j) {
            const int cj = (cnts >> (8 * j)) & 0xFF;
            const unsigned* __restrict__ lst =
                reinterpret_cast<const unsigned*>(&sList[buf][j][0]);
            for (int i = 0; i < cj; i += 4) {     // padded entries hit zero row
                const unsigned w4 = lst[i >> 2];
                accA += wp[(w4 & 0xFFu) * Nn];
                accB += wp[((w4 >> 8) & 0xFFu) * Nn];
                accA += wp[((w4 >> 16) & 0xFFu) * Nn];
                accB += wp[(w4 >> 24) * Nn];
            }
        }
        rec = rec * 0.95f + (accA + accB);

        x = xn;
    }

    // ---- final trace for this CTA's rows ----
    {
        float* tb = out + 2 * MEMOFF + n;
#pragma unroll
        for (int i = 0; i < SLOTS; ++i) {
            const int row = cta + GRID * i;
            if (row < Bb) tb[(size_t)row * Nn] = trc;
        }
    }
}

// ---------------------------------------------------------------------------
// Harness entry
// ---------------------------------------------------------------------------
extern "C" void kernel_launch(void* const* d_in, const int* in_sizes, int n_in,
                              void* d_out, int out_size) {
    const float* sig   = (const float*)d_in[0];  // (1000, 64)
    const float* w_in  = (const float*)d_in[1];  // (64, 128)
    const float* w_rec = (const float*)d_in[2];  // (128, 128)
    float* out = (float*)d_out;
    (void)in_sizes; (void)n_in; (void)out_size;

    const int smem = 129 * Nn * (int)sizeof(float);  // 66048 B
    cudaFuncSetAttribute(sim_kernel,
                         cudaFuncAttributeMaxDynamicSharedMemorySize, smem);

    inp_cur_kernel<<<Tn, Nn>>>(sig, w_in);
    sim_kernel<<<GRID, 128, smem>>>(w_rec, out);
}